// round 6
// baseline (speedup 1.0000x reference)
#include <cuda_runtime.h>
#include <cuda_bf16.h>
#include <cstdint>

// smem: X hi/lo = 256x128 bf16 (row stride 256B, XOR-swizzled). W hi/lo = 128x128 bf16
// ([k][n]); after GEMM1 reused as XW hi/lo. After GEMM3 the X region is reused as an
// f32 staging buffer for the cross-warp oa reduction. SUMS = per-warp row sums.
#define XH_OFF 0
#define XL_OFF 65536
#define WH_OFF 131072
#define WL_OFF 163840
#define SUMA_OFF 196608
#define SUMM_OFF 197632
#define SMEM_TOTAL 198656

__device__ __forceinline__ uint32_t smem_u32(const void* p) {
    uint32_t a;
    asm("{ .reg .u64 t; cvta.to.shared.u64 t, %1; cvt.u32.u64 %0, t; }" : "=r"(a) : "l"(p));
    return a;
}
__device__ __forceinline__ uint32_t soff(uint32_t region, int row, int byte) {
    return region + (uint32_t)(row * 256 + (byte ^ ((row & 7) << 4)));
}
__device__ __forceinline__ void ldsm4(uint32_t addr, uint32_t (&r)[4]) {
    asm volatile("ldmatrix.sync.aligned.m8n8.x4.shared.b16 {%0,%1,%2,%3}, [%4];"
                 : "=r"(r[0]), "=r"(r[1]), "=r"(r[2]), "=r"(r[3]) : "r"(addr));
}
__device__ __forceinline__ void ldsm4t(uint32_t addr, uint32_t (&r)[4]) {
    asm volatile("ldmatrix.sync.aligned.m8n8.x4.trans.shared.b16 {%0,%1,%2,%3}, [%4];"
                 : "=r"(r[0]), "=r"(r[1]), "=r"(r[2]), "=r"(r[3]) : "r"(addr));
}
__device__ __forceinline__ void mma16816(float (&c)[4], const uint32_t (&a)[4],
                                         uint32_t b0, uint32_t b1) {
    asm volatile("mma.sync.aligned.m16n8k16.row.col.f32.bf16.bf16.f32 "
                 "{%0,%1,%2,%3}, {%4,%5,%6,%7}, {%8,%9}, {%0,%1,%2,%3};"
                 : "+f"(c[0]), "+f"(c[1]), "+f"(c[2]), "+f"(c[3])
                 : "r"(a[0]), "r"(a[1]), "r"(a[2]), "r"(a[3]), "r"(b0), "r"(b1));
}
__device__ __forceinline__ uint32_t bpack(float x, float y) {
    __nv_bfloat162 h = __floats2bfloat162_rn(x, y);
    return *reinterpret_cast<uint32_t*>(&h);
}
__device__ __forceinline__ uint32_t bpacklo(float x, float y) {
    float hx = __bfloat162float(__float2bfloat16_rn(x));
    float hy = __bfloat162float(__float2bfloat16_rn(y));
    return bpack(x - hx, y - hy);
}

__global__ void __launch_bounds__(512, 1)
sattn_mma_kernel(const float* __restrict__ words, const float* __restrict__ Wm,
                 const int* __restrict__ vlen, float* __restrict__ out)
{
    extern __shared__ __align__(1024) char smem[];
    const uint32_t sb = smem_u32(smem);
    const int tid = threadIdx.x, lane = tid & 31, warp = tid >> 5;
    const int group = warp >> 1, side = warp & 1;
    const int sent = blockIdx.x >> 1, q0 = (blockIdx.x & 1) * 128;
    const float* xg = words + (size_t)sent * 256 * 128;
    const int len = vlen[sent];
    const int g = lane >> 2, q4 = lane & 3;

    // ---- load X -> XH/XL ----
    for (int i = tid; i < 8192; i += 512) {
        float4 v = ((const float4*)xg)[i];
        int t = i >> 5, b = (i & 31) << 3;
        uint2 hw, lw;
        hw.x = bpack(v.x, v.y); hw.y = bpack(v.z, v.w);
        lw.x = bpacklo(v.x, v.y); lw.y = bpacklo(v.z, v.w);
        *(uint2*)(smem + soff(XH_OFF, t, b)) = hw;
        *(uint2*)(smem + soff(XL_OFF, t, b)) = lw;
    }
    // ---- load W ([k][n]) -> WH/WL ----
    for (int i = tid; i < 4096; i += 512) {
        float4 v = ((const float4*)Wm)[i];
        int k = i >> 5, b = (i & 31) << 3;
        uint2 hw, lw;
        hw.x = bpack(v.x, v.y); hw.y = bpack(v.z, v.w);
        lw.x = bpacklo(v.x, v.y); lw.y = bpacklo(v.z, v.w);
        *(uint2*)(smem + soff(WH_OFF, k, b)) = hw;
        *(uint2*)(smem + soff(WL_OFF, k, b)) = lw;
    }
    __syncthreads();

    const int r0 = q0 + group * 16;

    // ===== GEMM1: XW[16 x 64(side)] = Xq @ W[:, side half] (3-pass split) =====
    {
        float xw[8][4];
        #pragma unroll
        for (int j = 0; j < 8; ++j) { xw[j][0] = xw[j][1] = xw[j][2] = xw[j][3] = 0.f; }

        #pragma unroll
        for (int kt = 0; kt < 8; ++kt) {
            uint32_t Ah[4], Al[4];
            {
                int row = r0 + (lane & 15);
                int byt = kt * 32 + ((lane >> 4) << 4);
                ldsm4(sb + soff(XH_OFF, row, byt), Ah);
                ldsm4(sb + soff(XL_OFF, row, byt), Al);
            }
            #pragma unroll
            for (int nnl = 0; nnl < 4; ++nnl) {
                int nn = side * 4 + nnl;
                uint32_t Bh[4], Bl[4];
                int rr = kt * 16 + (lane & 7) + (((lane >> 3) & 1) << 3);
                int bb = (nn * 16 + ((lane >> 4) << 3)) * 2;
                ldsm4t(sb + soff(WH_OFF, rr, bb), Bh);
                ldsm4t(sb + soff(WL_OFF, rr, bb), Bl);
                mma16816(xw[2 * nnl],     Ah, Bh[0], Bh[1]);
                mma16816(xw[2 * nnl + 1], Ah, Bh[2], Bh[3]);
                mma16816(xw[2 * nnl],     Ah, Bl[0], Bl[1]);
                mma16816(xw[2 * nnl + 1], Ah, Bl[2], Bl[3]);
                mma16816(xw[2 * nnl],     Al, Bh[0], Bh[1]);
                mma16816(xw[2 * nnl + 1], Al, Bh[2], Bh[3]);
            }
        }
        __syncthreads();   // all warps done reading W

        // store XW hi/lo (own 64 cols) into the W region
        #pragma unroll
        for (int j = 0; j < 8; ++j) {
            int nbyte = 2 * (side * 64 + 8 * j + 2 * q4);
            *(uint32_t*)(smem + soff(WH_OFF, group * 16 + g,     nbyte)) = bpack(xw[j][0], xw[j][1]);
            *(uint32_t*)(smem + soff(WL_OFF, group * 16 + g,     nbyte)) = bpacklo(xw[j][0], xw[j][1]);
            *(uint32_t*)(smem + soff(WH_OFF, group * 16 + g + 8, nbyte)) = bpack(xw[j][2], xw[j][3]);
            *(uint32_t*)(smem + soff(WL_OFF, group * 16 + g + 8, nbyte)) = bpacklo(xw[j][2], xw[j][3]);
        }
        __syncthreads();   // full XW visible to pair partner
    }

    // ===== per 64-key quarter of this warp's 128-key half:
    //       GEMM2 -> exp/mask -> partial GEMM3 (unnormalized) =====
    float oa[16][4];
    #pragma unroll
    for (int j = 0; j < 16; ++j) { oa[j][0] = oa[j][1] = oa[j][2] = oa[j][3] = 0.f; }
    float sa0 = 0.f, sm0 = 0.f, sa1 = 0.f, sm1 = 0.f;

    #pragma unroll
    for (int qt = 0; qt < 2; ++qt) {
        const int kb = side * 128 + qt * 64;
        float la[8][4];
        #pragma unroll
        for (int j = 0; j < 8; ++j) { la[j][0] = la[j][1] = la[j][2] = la[j][3] = 0.f; }

        // GEMM2 quarter: L[16 x 64] = XW @ X[kb..kb+64]^T
        #pragma unroll
        for (int kt = 0; kt < 8; ++kt) {
            uint32_t Ah[4], Al[4];
            {
                int row = group * 16 + (lane & 15);
                int byt = kt * 32 + ((lane >> 4) << 4);
                ldsm4(sb + soff(WH_OFF, row, byt), Ah);
                ldsm4(sb + soff(WL_OFF, row, byt), Al);
            }
            #pragma unroll
            for (int nn = 0; nn < 4; ++nn) {
                uint32_t Bh[4], Bl[4];
                int rr = kb + nn * 16 + (lane & 7) + ((lane >> 4) << 3);
                int bb = kt * 32 + (((lane >> 3) & 1) << 4);
                ldsm4(sb + soff(XH_OFF, rr, bb), Bh);
                ldsm4(sb + soff(XL_OFF, rr, bb), Bl);
                mma16816(la[2 * nn],     Ah, Bh[0], Bh[1]);
                mma16816(la[2 * nn + 1], Ah, Bh[2], Bh[3]);
                mma16816(la[2 * nn],     Ah, Bl[0], Bl[1]);
                mma16816(la[2 * nn + 1], Ah, Bl[2], Bl[3]);
                mma16816(la[2 * nn],     Al, Bh[0], Bh[1]);
                mma16816(la[2 * nn + 1], Al, Bh[2], Bh[3]);
            }
        }

        // tanh -> exp -> mask (unnormalized; row sums accumulated)
        #pragma unroll
        for (int j = 0; j < 8; ++j) {
            int tb = kb + 8 * j + 2 * q4;
            #pragma unroll
            for (int c = 0; c < 2; ++c) {
                const bool m = (tb + c) < len;
                {
                    float l = la[j][c];
                    float u = __expf(2.f * l);
                    float t2 = 1.f - __fdividef(2.f, u + 1.f);
                    float w = __expf(t2);
                    float wm = m ? w : 0.f;
                    sa0 += w; sm0 += wm; la[j][c] = wm;
                }
                {
                    float l = la[j][2 + c];
                    float u = __expf(2.f * l);
                    float t2 = 1.f - __fdividef(2.f, u + 1.f);
                    float w = __expf(t2);
                    float wm = m ? w : 0.f;
                    sa1 += w; sm1 += wm; la[j][2 + c] = wm;
                }
            }
        }

        // GEMM3 partial: oa += w_quarter @ X[kb..kb+64]
        #pragma unroll
        for (int kt = 0; kt < 4; ++kt) {
            uint32_t ph[4], pl[4];
            ph[0] = bpack(la[2 * kt][0], la[2 * kt][1]);
            ph[1] = bpack(la[2 * kt][2], la[2 * kt][3]);
            ph[2] = bpack(la[2 * kt + 1][0], la[2 * kt + 1][1]);
            ph[3] = bpack(la[2 * kt + 1][2], la[2 * kt + 1][3]);
            pl[0] = bpacklo(la[2 * kt][0], la[2 * kt][1]);
            pl[1] = bpacklo(la[2 * kt][2], la[2 * kt][3]);
            pl[2] = bpacklo(la[2 * kt + 1][0], la[2 * kt + 1][1]);
            pl[3] = bpacklo(la[2 * kt + 1][2], la[2 * kt + 1][3]);
            #pragma unroll
            for (int nn = 0; nn < 8; ++nn) {
                uint32_t Bh[4], Bl[4];
                int rr = kb + kt * 16 + (lane & 7) + (((lane >> 3) & 1) << 3);
                int bb = (nn * 16 + ((lane >> 4) << 3)) * 2;
                ldsm4t(sb + soff(XH_OFF, rr, bb), Bh);
                ldsm4t(sb + soff(XL_OFF, rr, bb), Bl);
                mma16816(oa[2 * nn],     ph, Bh[0], Bh[1]);
                mma16816(oa[2 * nn + 1], ph, Bh[2], Bh[3]);
                mma16816(oa[2 * nn],     ph, Bl[0], Bl[1]);
                mma16816(oa[2 * nn + 1], ph, Bl[2], Bl[3]);
                mma16816(oa[2 * nn],     pl, Bh[0], Bh[1]);
                mma16816(oa[2 * nn + 1], pl, Bh[2], Bh[3]);
            }
        }
    }

    // ===== per-warp row sums -> smem =====
    #pragma unroll
    for (int off = 1; off <= 2; off <<= 1) {
        sa0 += __shfl_xor_sync(0xffffffffu, sa0, off);
        sm0 += __shfl_xor_sync(0xffffffffu, sm0, off);
        sa1 += __shfl_xor_sync(0xffffffffu, sa1, off);
        sm1 += __shfl_xor_sync(0xffffffffu, sm1, off);
    }
    if (q4 == 0) {
        *(float*)(smem + SUMA_OFF + (warp * 16 + g) * 4) = sa0;
        *(float*)(smem + SUMA_OFF + (warp * 16 + g + 8) * 4) = sa1;
        *(float*)(smem + SUMM_OFF + (warp * 16 + g) * 4) = sm0;
        *(float*)(smem + SUMM_OFF + (warp * 16 + g + 8) * 4) = sm1;
    }
    __syncthreads();   // X reads done everywhere; sums visible

    // ===== cross-pair reduction: side 0 stages oa into dead X region =====
    float* stg = (float*)(smem + group * 8448);   // 16 rows x 132-float stride
    if (side == 0) {
        #pragma unroll
        for (int j = 0; j < 16; ++j) {
            int col = 8 * j + 2 * q4;
            *(float2*)(stg + g * 132 + col)       = make_float2(oa[j][0], oa[j][1]);
            *(float2*)(stg + (g + 8) * 132 + col) = make_float2(oa[j][2], oa[j][3]);
        }
    }
    __syncthreads();
    if (side == 1) {
        const float* SA = (const float*)(smem + SUMA_OFF);
        const float* SM = (const float*)(smem + SUMM_OFF);
        const int w0 = group * 2, w1 = group * 2 + 1;
        const float sA0 = SA[w0 * 16 + g]     + SA[w1 * 16 + g];
        const float sM0 = SM[w0 * 16 + g]     + SM[w1 * 16 + g];
        const float sA1 = SA[w0 * 16 + g + 8] + SA[w1 * 16 + g + 8];
        const float sM1 = SM[w0 * 16 + g + 8] + SM[w1 * 16 + g + 8];
        const float inv0 = 1.f / (sM0 + 1e-8f * sA0);
        const float inv1 = 1.f / (sM1 + 1e-8f * sA1);
        const size_t rbase = (size_t)sent * 256 + r0;
        #pragma unroll
        for (int j = 0; j < 16; ++j) {
            int col = 8 * j + 2 * q4;
            float2 s0 = *(float2*)(stg + g * 132 + col);
            float2 s1 = *(float2*)(stg + (g + 8) * 132 + col);
            float2 v0; v0.x = (oa[j][0] + s0.x) * inv0; v0.y = (oa[j][1] + s0.y) * inv0;
            float2 v1; v1.x = (oa[j][2] + s1.x) * inv1; v1.y = (oa[j][3] + s1.y) * inv1;
            *(float2*)(out + (rbase + g) * 128 + col) = v0;
            *(float2*)(out + (rbase + g + 8) * 128 + col) = v1;
        }
    }
}

extern "C" void kernel_launch(void* const* d_in, const int* in_sizes, int n_in,
                              void* d_out, int out_size)
{
    const float* words = (const float*)d_in[0];
    const float* Wm    = (const float*)d_in[1];
    const int*   vlen  = (const int*)d_in[2];
    float* out = (float*)d_out;

    cudaFuncSetAttribute(sattn_mma_kernel,
                         cudaFuncAttributeMaxDynamicSharedMemorySize, SMEM_TOTAL);
    sattn_mma_kernel<<<1024, 512, SMEM_TOTAL>>>(words, Wm, vlen, out);
}

// round 7
// speedup vs baseline: 1.0146x; 1.0146x over previous
#include <cuda_runtime.h>
#include <cuda_bf16.h>
#include <cstdint>

// smem: X hi/lo = 256x128 bf16 (row stride 256B, XOR-swizzled). W hi/lo = 128x128 bf16
// ([k][n]); after GEMM1 reused as XW hi/lo. After GEMM3 the X region is reused as an
// f32 staging buffer for the cross-warp oa reduction. SUMS = per-warp row sums.
#define XH_OFF 0
#define XL_OFF 65536
#define WH_OFF 131072
#define WL_OFF 163840
#define SUMA_OFF 196608
#define SUMM_OFF 197632
#define SMEM_TOTAL 198656

__device__ __forceinline__ uint32_t smem_u32(const void* p) {
    uint32_t a;
    asm("{ .reg .u64 t; cvta.to.shared.u64 t, %1; cvt.u32.u64 %0, t; }" : "=r"(a) : "l"(p));
    return a;
}
__device__ __forceinline__ uint32_t soff(uint32_t region, int row, int byte) {
    return region + (uint32_t)(row * 256 + (byte ^ ((row & 7) << 4)));
}
__device__ __forceinline__ void ldsm4(uint32_t addr, uint32_t (&r)[4]) {
    asm volatile("ldmatrix.sync.aligned.m8n8.x4.shared.b16 {%0,%1,%2,%3}, [%4];"
                 : "=r"(r[0]), "=r"(r[1]), "=r"(r[2]), "=r"(r[3]) : "r"(addr));
}
__device__ __forceinline__ void ldsm4t(uint32_t addr, uint32_t (&r)[4]) {
    asm volatile("ldmatrix.sync.aligned.m8n8.x4.trans.shared.b16 {%0,%1,%2,%3}, [%4];"
                 : "=r"(r[0]), "=r"(r[1]), "=r"(r[2]), "=r"(r[3]) : "r"(addr));
}
__device__ __forceinline__ void mma16816(float (&c)[4], const uint32_t (&a)[4],
                                         uint32_t b0, uint32_t b1) {
    asm volatile("mma.sync.aligned.m16n8k16.row.col.f32.bf16.bf16.f32 "
                 "{%0,%1,%2,%3}, {%4,%5,%6,%7}, {%8,%9}, {%0,%1,%2,%3};"
                 : "+f"(c[0]), "+f"(c[1]), "+f"(c[2]), "+f"(c[3])
                 : "r"(a[0]), "r"(a[1]), "r"(a[2]), "r"(a[3]), "r"(b0), "r"(b1));
}
__device__ __forceinline__ uint32_t bpack(float x, float y) {
    __nv_bfloat162 h = __floats2bfloat162_rn(x, y);
    return *reinterpret_cast<uint32_t*>(&h);
}
__device__ __forceinline__ uint32_t bpacklo(float x, float y) {
    float hx = __bfloat162float(__float2bfloat16_rn(x));
    float hy = __bfloat162float(__float2bfloat16_rn(y));
    return bpack(x - hx, y - hy);
}

__global__ void __launch_bounds__(512, 1)
sattn_mma_kernel(const float* __restrict__ words, const float* __restrict__ Wm,
                 const int* __restrict__ vlen, float* __restrict__ out)
{
    extern __shared__ __align__(1024) char smem[];
    const uint32_t sb = smem_u32(smem);
    const int tid = threadIdx.x, lane = tid & 31, warp = tid >> 5;
    const int group = warp >> 1, side = warp & 1;
    const int sent = blockIdx.x >> 1, q0 = (blockIdx.x & 1) * 128;
    const float* xg = words + (size_t)sent * 256 * 128;
    const int len = vlen[sent];
    const int g = lane >> 2, q4 = lane & 3;

    // ---- load X -> XH/XL ----
    for (int i = tid; i < 8192; i += 512) {
        float4 v = ((const float4*)xg)[i];
        int t = i >> 5, b = (i & 31) << 3;
        uint2 hw, lw;
        hw.x = bpack(v.x, v.y); hw.y = bpack(v.z, v.w);
        lw.x = bpacklo(v.x, v.y); lw.y = bpacklo(v.z, v.w);
        *(uint2*)(smem + soff(XH_OFF, t, b)) = hw;
        *(uint2*)(smem + soff(XL_OFF, t, b)) = lw;
    }
    // ---- load W ([k][n]) -> WH/WL ----
    for (int i = tid; i < 4096; i += 512) {
        float4 v = ((const float4*)Wm)[i];
        int k = i >> 5, b = (i & 31) << 3;
        uint2 hw, lw;
        hw.x = bpack(v.x, v.y); hw.y = bpack(v.z, v.w);
        lw.x = bpacklo(v.x, v.y); lw.y = bpacklo(v.z, v.w);
        *(uint2*)(smem + soff(WH_OFF, k, b)) = hw;
        *(uint2*)(smem + soff(WL_OFF, k, b)) = lw;
    }
    __syncthreads();

    const int r0 = q0 + group * 16;

    // ===== GEMM1: XW[16 x 64(side)] = Xq @ W[:, side half] (3-pass split) =====
    {
        float xw[8][4];
        #pragma unroll
        for (int j = 0; j < 8; ++j) { xw[j][0] = xw[j][1] = xw[j][2] = xw[j][3] = 0.f; }

        #pragma unroll
        for (int kt = 0; kt < 8; ++kt) {
            uint32_t Ah[4], Al[4];
            {
                int row = r0 + (lane & 15);
                int byt = kt * 32 + ((lane >> 4) << 4);
                ldsm4(sb + soff(XH_OFF, row, byt), Ah);
                ldsm4(sb + soff(XL_OFF, row, byt), Al);
            }
            #pragma unroll
            for (int nnl = 0; nnl < 4; ++nnl) {
                int nn = side * 4 + nnl;
                uint32_t Bh[4], Bl[4];
                int rr = kt * 16 + (lane & 7) + (((lane >> 3) & 1) << 3);
                int bb = (nn * 16 + ((lane >> 4) << 3)) * 2;
                ldsm4t(sb + soff(WH_OFF, rr, bb), Bh);
                ldsm4t(sb + soff(WL_OFF, rr, bb), Bl);
                mma16816(xw[2 * nnl],     Ah, Bh[0], Bh[1]);
                mma16816(xw[2 * nnl + 1], Ah, Bh[2], Bh[3]);
                mma16816(xw[2 * nnl],     Ah, Bl[0], Bl[1]);
                mma16816(xw[2 * nnl + 1], Ah, Bl[2], Bl[3]);
                mma16816(xw[2 * nnl],     Al, Bh[0], Bh[1]);
                mma16816(xw[2 * nnl + 1], Al, Bh[2], Bh[3]);
            }
        }
        __syncthreads();   // all warps done reading W

        // store XW hi/lo (own 64 cols) into the W region
        #pragma unroll
        for (int j = 0; j < 8; ++j) {
            int nbyte = 2 * (side * 64 + 8 * j + 2 * q4);
            *(uint32_t*)(smem + soff(WH_OFF, group * 16 + g,     nbyte)) = bpack(xw[j][0], xw[j][1]);
            *(uint32_t*)(smem + soff(WL_OFF, group * 16 + g,     nbyte)) = bpacklo(xw[j][0], xw[j][1]);
            *(uint32_t*)(smem + soff(WH_OFF, group * 16 + g + 8, nbyte)) = bpack(xw[j][2], xw[j][3]);
            *(uint32_t*)(smem + soff(WL_OFF, group * 16 + g + 8, nbyte)) = bpacklo(xw[j][2], xw[j][3]);
        }
        __syncthreads();   // full XW visible to pair partner
    }

    // ===== fused per 16-key tile over this warp's 128-key half:
    //       GEMM2(16 keys) -> exp/mask -> partial GEMM3 (unnormalized) =====
    float oa[16][4];
    #pragma unroll
    for (int j = 0; j < 16; ++j) { oa[j][0] = oa[j][1] = oa[j][2] = oa[j][3] = 0.f; }
    float sa0 = 0.f, sm0 = 0.f, sa1 = 0.f, sm1 = 0.f;

    #pragma unroll
    for (int ti = 0; ti < 8; ++ti) {
        const int kb = side * 128 + ti * 16;
        float la[2][4];
        la[0][0] = la[0][1] = la[0][2] = la[0][3] = 0.f;
        la[1][0] = la[1][1] = la[1][2] = la[1][3] = 0.f;

        // GEMM2 tile: L[16 x 16] = XW @ X[kb..kb+16]^T
        #pragma unroll
        for (int kt = 0; kt < 8; ++kt) {
            uint32_t Ah[4], Al[4];
            {
                int row = group * 16 + (lane & 15);
                int byt = kt * 32 + ((lane >> 4) << 4);
                ldsm4(sb + soff(WH_OFF, row, byt), Ah);
                ldsm4(sb + soff(WL_OFF, row, byt), Al);
            }
            uint32_t Bh[4], Bl[4];
            int rr = kb + (lane & 7) + ((lane >> 4) << 3);
            int bb = kt * 32 + (((lane >> 3) & 1) << 4);
            ldsm4(sb + soff(XH_OFF, rr, bb), Bh);
            ldsm4(sb + soff(XL_OFF, rr, bb), Bl);
            mma16816(la[0], Ah, Bh[0], Bh[1]);
            mma16816(la[1], Ah, Bh[2], Bh[3]);
            mma16816(la[0], Ah, Bl[0], Bl[1]);
            mma16816(la[1], Ah, Bl[2], Bl[3]);
            mma16816(la[0], Al, Bh[0], Bh[1]);
            mma16816(la[1], Al, Bh[2], Bh[3]);
        }

        // tanh -> exp -> mask (unnormalized; row sums accumulated)
        #pragma unroll
        for (int j = 0; j < 2; ++j) {
            int tb = kb + 8 * j + 2 * q4;
            #pragma unroll
            for (int c = 0; c < 2; ++c) {
                const bool m = (tb + c) < len;
                {
                    float l = la[j][c];
                    float u = __expf(2.f * l);
                    float t2 = 1.f - __fdividef(2.f, u + 1.f);
                    float w = __expf(t2);
                    float wm = m ? w : 0.f;
                    sa0 += w; sm0 += wm; la[j][c] = wm;
                }
                {
                    float l = la[j][2 + c];
                    float u = __expf(2.f * l);
                    float t2 = 1.f - __fdividef(2.f, u + 1.f);
                    float w = __expf(t2);
                    float wm = m ? w : 0.f;
                    sa1 += w; sm1 += wm; la[j][2 + c] = wm;
                }
            }
        }

        // GEMM3 partial: oa += w_tile @ X[kb..kb+16]
        uint32_t ph[4], pl[4];
        ph[0] = bpack(la[0][0], la[0][1]);
        ph[1] = bpack(la[0][2], la[0][3]);
        ph[2] = bpack(la[1][0], la[1][1]);
        ph[3] = bpack(la[1][2], la[1][3]);
        pl[0] = bpacklo(la[0][0], la[0][1]);
        pl[1] = bpacklo(la[0][2], la[0][3]);
        pl[2] = bpacklo(la[1][0], la[1][1]);
        pl[3] = bpacklo(la[1][2], la[1][3]);
        #pragma unroll
        for (int nn = 0; nn < 8; ++nn) {
            uint32_t Bh[4], Bl[4];
            int rr = kb + (lane & 7) + (((lane >> 3) & 1) << 3);
            int bb = (nn * 16 + ((lane >> 4) << 3)) * 2;
            ldsm4t(sb + soff(XH_OFF, rr, bb), Bh);
            ldsm4t(sb + soff(XL_OFF, rr, bb), Bl);
            mma16816(oa[2 * nn],     ph, Bh[0], Bh[1]);
            mma16816(oa[2 * nn + 1], ph, Bh[2], Bh[3]);
            mma16816(oa[2 * nn],     ph, Bl[0], Bl[1]);
            mma16816(oa[2 * nn + 1], ph, Bl[2], Bl[3]);
            mma16816(oa[2 * nn],     pl, Bh[0], Bh[1]);
            mma16816(oa[2 * nn + 1], pl, Bh[2], Bh[3]);
        }
    }

    // ===== per-warp row sums -> smem =====
    #pragma unroll
    for (int off = 1; off <= 2; off <<= 1) {
        sa0 += __shfl_xor_sync(0xffffffffu, sa0, off);
        sm0 += __shfl_xor_sync(0xffffffffu, sm0, off);
        sa1 += __shfl_xor_sync(0xffffffffu, sa1, off);
        sm1 += __shfl_xor_sync(0xffffffffu, sm1, off);
    }
    if (q4 == 0) {
        *(float*)(smem + SUMA_OFF + (warp * 16 + g) * 4) = sa0;
        *(float*)(smem + SUMA_OFF + (warp * 16 + g + 8) * 4) = sa1;
        *(float*)(smem + SUMM_OFF + (warp * 16 + g) * 4) = sm0;
        *(float*)(smem + SUMM_OFF + (warp * 16 + g + 8) * 4) = sm1;
    }
    __syncthreads();   // X reads done everywhere; sums visible

    // ===== cross-pair reduction: side 0 stages oa into dead X region =====
    float* stg = (float*)(smem + group * 8448);   // 16 rows x 132-float stride
    if (side == 0) {
        #pragma unroll
        for (int j = 0; j < 16; ++j) {
            int col = 8 * j + 2 * q4;
            *(float2*)(stg + g * 132 + col)       = make_float2(oa[j][0], oa[j][1]);
            *(float2*)(stg + (g + 8) * 132 + col) = make_float2(oa[j][2], oa[j][3]);
        }
    }
    __syncthreads();
    if (side == 1) {
        const float* SA = (const float*)(smem + SUMA_OFF);
        const float* SM = (const float*)(smem + SUMM_OFF);
        const int w0 = group * 2, w1 = group * 2 + 1;
        const float sA0 = SA[w0 * 16 + g]     + SA[w1 * 16 + g];
        const float sM0 = SM[w0 * 16 + g]     + SM[w1 * 16 + g];
        const float sA1 = SA[w0 * 16 + g + 8] + SA[w1 * 16 + g + 8];
        const float sM1 = SM[w0 * 16 + g + 8] + SM[w1 * 16 + g + 8];
        const float inv0 = 1.f / (sM0 + 1e-8f * sA0);
        const float inv1 = 1.f / (sM1 + 1e-8f * sA1);
        const size_t rbase = (size_t)sent * 256 + r0;
        #pragma unroll
        for (int j = 0; j < 16; ++j) {
            int col = 8 * j + 2 * q4;
            float2 s0 = *(float2*)(stg + g * 132 + col);
            float2 s1 = *(float2*)(stg + (g + 8) * 132 + col);
            float2 v0; v0.x = (oa[j][0] + s0.x) * inv0; v0.y = (oa[j][1] + s0.y) * inv0;
            float2 v1; v1.x = (oa[j][2] + s1.x) * inv1; v1.y = (oa[j][3] + s1.y) * inv1;
            *(float2*)(out + (rbase + g) * 128 + col) = v0;
            *(float2*)(out + (rbase + g + 8) * 128 + col) = v1;
        }
    }
}

extern "C" void kernel_launch(void* const* d_in, const int* in_sizes, int n_in,
                              void* d_out, int out_size)
{
    const float* words = (const float*)d_in[0];
    const float* Wm    = (const float*)d_in[1];
    const int*   vlen  = (const int*)d_in[2];
    float* out = (float*)d_out;

    cudaFuncSetAttribute(sattn_mma_kernel,
                         cudaFuncAttributeMaxDynamicSharedMemorySize, SMEM_TOTAL);
    sattn_mma_kernel<<<1024, 512, SMEM_TOTAL>>>(words, Wm, vlen, out);
}

// round 8
// speedup vs baseline: 1.1912x; 1.1741x over previous
#include <cuda_runtime.h>
#include <cuda_bf16.h>
#include <cstdint>

// smem: X hi/lo = 256x128 bf16 (row stride 256B, XOR-swizzled). W hi/lo = 128x128 bf16
// ([k][n]); after GEMM1 the W region is reused as XW hi/lo.
#define XH_OFF 0
#define XL_OFF 65536
#define WH_OFF 131072
#define WL_OFF 163840
#define SMEM_TOTAL 196608

__device__ __forceinline__ uint32_t smem_u32(const void* p) {
    uint32_t a;
    asm("{ .reg .u64 t; cvta.to.shared.u64 t, %1; cvt.u32.u64 %0, t; }" : "=r"(a) : "l"(p));
    return a;
}
__device__ __forceinline__ uint32_t soff(uint32_t region, int row, int byte) {
    return region + (uint32_t)(row * 256 + (byte ^ ((row & 7) << 4)));
}
__device__ __forceinline__ void ldsm4(uint32_t addr, uint32_t (&r)[4]) {
    asm volatile("ldmatrix.sync.aligned.m8n8.x4.shared.b16 {%0,%1,%2,%3}, [%4];"
                 : "=r"(r[0]), "=r"(r[1]), "=r"(r[2]), "=r"(r[3]) : "r"(addr));
}
__device__ __forceinline__ void ldsm4t(uint32_t addr, uint32_t (&r)[4]) {
    asm volatile("ldmatrix.sync.aligned.m8n8.x4.trans.shared.b16 {%0,%1,%2,%3}, [%4];"
                 : "=r"(r[0]), "=r"(r[1]), "=r"(r[2]), "=r"(r[3]) : "r"(addr));
}
__device__ __forceinline__ void mma16816(float (&c)[4], const uint32_t (&a)[4],
                                         uint32_t b0, uint32_t b1) {
    asm volatile("mma.sync.aligned.m16n8k16.row.col.f32.bf16.bf16.f32 "
                 "{%0,%1,%2,%3}, {%4,%5,%6,%7}, {%8,%9}, {%0,%1,%2,%3};"
                 : "+f"(c[0]), "+f"(c[1]), "+f"(c[2]), "+f"(c[3])
                 : "r"(a[0]), "r"(a[1]), "r"(a[2]), "r"(a[3]), "r"(b0), "r"(b1));
}
__device__ __forceinline__ uint32_t bpack(float x, float y) {
    __nv_bfloat162 h = __floats2bfloat162_rn(x, y);
    return *reinterpret_cast<uint32_t*>(&h);
}
__device__ __forceinline__ uint32_t bpacklo(float x, float y) {
    float hx = __bfloat162float(__float2bfloat16_rn(x));
    float hy = __bfloat162float(__float2bfloat16_rn(y));
    return bpack(x - hx, y - hy);
}

__global__ void __launch_bounds__(256, 1)
sattn_mma_kernel(const float* __restrict__ words, const float* __restrict__ Wm,
                 const int* __restrict__ vlen, float* __restrict__ out)
{
    extern __shared__ __align__(1024) char smem[];
    const uint32_t sb = smem_u32(smem);
    const int tid = threadIdx.x, lane = tid & 31, warp = tid >> 5;
    const int sent = blockIdx.x >> 1, q0 = (blockIdx.x & 1) * 128;
    const float* xg = words + (size_t)sent * 256 * 128;
    const int len = vlen[sent];
    const int g = lane >> 2, q4 = lane & 3;

    // ---- load X -> XH/XL ----
    for (int i = tid; i < 8192; i += 256) {
        float4 v = ((const float4*)xg)[i];
        int t = i >> 5, b = (i & 31) << 3;
        uint2 hw, lw;
        hw.x = bpack(v.x, v.y); hw.y = bpack(v.z, v.w);
        lw.x = bpacklo(v.x, v.y); lw.y = bpacklo(v.z, v.w);
        *(uint2*)(smem + soff(XH_OFF, t, b)) = hw;
        *(uint2*)(smem + soff(XL_OFF, t, b)) = lw;
    }
    // ---- load W ([k][n]) -> WH/WL ----
    for (int i = tid; i < 4096; i += 256) {
        float4 v = ((const float4*)Wm)[i];
        int k = i >> 5, b = (i & 31) << 3;
        uint2 hw, lw;
        hw.x = bpack(v.x, v.y); hw.y = bpack(v.z, v.w);
        lw.x = bpacklo(v.x, v.y); lw.y = bpacklo(v.z, v.w);
        *(uint2*)(smem + soff(WH_OFF, k, b)) = hw;
        *(uint2*)(smem + soff(WL_OFF, k, b)) = lw;
    }
    __syncthreads();

    const int r0 = q0 + warp * 16;

    // ===== GEMM1: XW[16 x 128] = Xq @ W (3-pass split) =====
    {
        float xw[16][4];
        #pragma unroll
        for (int j = 0; j < 16; ++j) { xw[j][0] = xw[j][1] = xw[j][2] = xw[j][3] = 0.f; }

        #pragma unroll
        for (int kt = 0; kt < 8; ++kt) {
            uint32_t Ah[4], Al[4];
            {
                int row = r0 + (lane & 15);
                int byt = kt * 32 + ((lane >> 4) << 4);
                ldsm4(sb + soff(XH_OFF, row, byt), Ah);
                ldsm4(sb + soff(XL_OFF, row, byt), Al);
            }
            #pragma unroll
            for (int nn = 0; nn < 8; ++nn) {
                uint32_t Bh[4], Bl[4];
                int rr = kt * 16 + (lane & 7) + (((lane >> 3) & 1) << 3);
                int bb = (nn * 16 + ((lane >> 4) << 3)) * 2;
                ldsm4t(sb + soff(WH_OFF, rr, bb), Bh);
                ldsm4t(sb + soff(WL_OFF, rr, bb), Bl);
                mma16816(xw[2 * nn],     Ah, Bh[0], Bh[1]);
                mma16816(xw[2 * nn + 1], Ah, Bh[2], Bh[3]);
                mma16816(xw[2 * nn],     Ah, Bl[0], Bl[1]);
                mma16816(xw[2 * nn + 1], Ah, Bl[2], Bl[3]);
                mma16816(xw[2 * nn],     Al, Bh[0], Bh[1]);
                mma16816(xw[2 * nn + 1], Al, Bh[2], Bh[3]);
            }
        }
        __syncthreads();   // all warps done reading W

        // store XW hi/lo into the W region (rows are warp-private)
        #pragma unroll
        for (int j = 0; j < 16; ++j) {
            int nbyte = 2 * (8 * j + 2 * q4);
            *(uint32_t*)(smem + soff(WH_OFF, warp * 16 + g,     nbyte)) = bpack(xw[j][0], xw[j][1]);
            *(uint32_t*)(smem + soff(WL_OFF, warp * 16 + g,     nbyte)) = bpacklo(xw[j][0], xw[j][1]);
            *(uint32_t*)(smem + soff(WH_OFF, warp * 16 + g + 8, nbyte)) = bpack(xw[j][2], xw[j][3]);
            *(uint32_t*)(smem + soff(WL_OFF, warp * 16 + g + 8, nbyte)) = bpacklo(xw[j][2], xw[j][3]);
        }
        __syncwarp();
    }

    // ===== fused per 32-key tile over all 256 keys:
    //       GEMM2(32 keys) -> exp/mask -> partial GEMM3 (unnormalized) =====
    float oa[16][4];
    #pragma unroll
    for (int j = 0; j < 16; ++j) { oa[j][0] = oa[j][1] = oa[j][2] = oa[j][3] = 0.f; }
    float sa0 = 0.f, sm0 = 0.f, sa1 = 0.f, sm1 = 0.f;

    #pragma unroll
    for (int ti = 0; ti < 8; ++ti) {
        const int kb = ti * 32;
        float la[4][4];
        #pragma unroll
        for (int j = 0; j < 4; ++j) { la[j][0] = la[j][1] = la[j][2] = la[j][3] = 0.f; }

        // GEMM2 tile: L[16 x 32] = XW @ X[kb..kb+32]^T (4-acc rotation)
        #pragma unroll
        for (int kt = 0; kt < 8; ++kt) {
            uint32_t Ah[4], Al[4];
            {
                int row = warp * 16 + (lane & 15);
                int byt = kt * 32 + ((lane >> 4) << 4);
                ldsm4(sb + soff(WH_OFF, row, byt), Ah);
                ldsm4(sb + soff(WL_OFF, row, byt), Al);
            }
            uint32_t B0h[4], B0l[4], B1h[4], B1l[4];
            int rrb = (lane & 7) + ((lane >> 4) << 3);
            int bb = kt * 32 + (((lane >> 3) & 1) << 4);
            ldsm4(sb + soff(XH_OFF, kb + rrb, bb), B0h);
            ldsm4(sb + soff(XL_OFF, kb + rrb, bb), B0l);
            ldsm4(sb + soff(XH_OFF, kb + 16 + rrb, bb), B1h);
            ldsm4(sb + soff(XL_OFF, kb + 16 + rrb, bb), B1l);
            mma16816(la[0], Ah, B0h[0], B0h[1]);
            mma16816(la[1], Ah, B0h[2], B0h[3]);
            mma16816(la[2], Ah, B1h[0], B1h[1]);
            mma16816(la[3], Ah, B1h[2], B1h[3]);
            mma16816(la[0], Ah, B0l[0], B0l[1]);
            mma16816(la[1], Ah, B0l[2], B0l[3]);
            mma16816(la[2], Ah, B1l[0], B1l[1]);
            mma16816(la[3], Ah, B1l[2], B1l[3]);
            mma16816(la[0], Al, B0h[0], B0h[1]);
            mma16816(la[1], Al, B0h[2], B0h[3]);
            mma16816(la[2], Al, B1h[0], B1h[1]);
            mma16816(la[3], Al, B1h[2], B1h[3]);
        }

        // tanh -> exp -> mask (unnormalized; row sums accumulated)
        #pragma unroll
        for (int j = 0; j < 4; ++j) {
            int tb = kb + 8 * j + 2 * q4;
            #pragma unroll
            for (int c = 0; c < 2; ++c) {
                const bool m = (tb + c) < len;
                {
                    float l = la[j][c];
                    float u = __expf(2.f * l);
                    float t2 = 1.f - __fdividef(2.f, u + 1.f);
                    float w = __expf(t2);
                    float wm = m ? w : 0.f;
                    sa0 += w; sm0 += wm; la[j][c] = wm;
                }
                {
                    float l = la[j][2 + c];
                    float u = __expf(2.f * l);
                    float t2 = 1.f - __fdividef(2.f, u + 1.f);
                    float w = __expf(t2);
                    float wm = m ? w : 0.f;
                    sa1 += w; sm1 += wm; la[j][2 + c] = wm;
                }
            }
        }

        // GEMM3 partial: oa += w_tile @ X[kb..kb+32] (two 16-key halves)
        #pragma unroll
        for (int h = 0; h < 2; ++h) {
            uint32_t ph[4], pl[4];
            ph[0] = bpack(la[2 * h][0], la[2 * h][1]);
            ph[1] = bpack(la[2 * h][2], la[2 * h][3]);
            ph[2] = bpack(la[2 * h + 1][0], la[2 * h + 1][1]);
            ph[3] = bpack(la[2 * h + 1][2], la[2 * h + 1][3]);
            pl[0] = bpacklo(la[2 * h][0], la[2 * h][1]);
            pl[1] = bpacklo(la[2 * h][2], la[2 * h][3]);
            pl[2] = bpacklo(la[2 * h + 1][0], la[2 * h + 1][1]);
            pl[3] = bpacklo(la[2 * h + 1][2], la[2 * h + 1][3]);
            #pragma unroll
            for (int nn = 0; nn < 8; ++nn) {
                uint32_t Bh[4], Bl[4];
                int rr = kb + h * 16 + (lane & 7) + (((lane >> 3) & 1) << 3);
                int bb = (nn * 16 + ((lane >> 4) << 3)) * 2;
                ldsm4t(sb + soff(XH_OFF, rr, bb), Bh);
                ldsm4t(sb + soff(XL_OFF, rr, bb), Bl);
                mma16816(oa[2 * nn],     ph, Bh[0], Bh[1]);
                mma16816(oa[2 * nn + 1], ph, Bh[2], Bh[3]);
                mma16816(oa[2 * nn],     ph, Bl[0], Bl[1]);
                mma16816(oa[2 * nn + 1], ph, Bl[2], Bl[3]);
                mma16816(oa[2 * nn],     pl, Bh[0], Bh[1]);
                mma16816(oa[2 * nn + 1], pl, Bh[2], Bh[3]);
            }
        }
    }

    // ===== row sums -> inverse -> scale -> store =====
    #pragma unroll
    for (int off = 1; off <= 2; off <<= 1) {
        sa0 += __shfl_xor_sync(0xffffffffu, sa0, off);
        sm0 += __shfl_xor_sync(0xffffffffu, sm0, off);
        sa1 += __shfl_xor_sync(0xffffffffu, sa1, off);
        sm1 += __shfl_xor_sync(0xffffffffu, sm1, off);
    }
    const float inv0 = 1.f / (sm0 + 1e-8f * sa0);
    const float inv1 = 1.f / (sm1 + 1e-8f * sa1);

    {
        const size_t rbase = (size_t)sent * 256 + r0;
        #pragma unroll
        for (int j = 0; j < 16; ++j) {
            int col = 8 * j + 2 * q4;
            float2 v0; v0.x = oa[j][0] * inv0; v0.y = oa[j][1] * inv0;
            float2 v1; v1.x = oa[j][2] * inv1; v1.y = oa[j][3] * inv1;
            *(float2*)(out + (rbase + g) * 128 + col) = v0;
            *(float2*)(out + (rbase + g + 8) * 128 + col) = v1;
        }
    }
}

extern "C" void kernel_launch(void* const* d_in, const int* in_sizes, int n_in,
                              void* d_out, int out_size)
{
    const float* words = (const float*)d_in[0];
    const float* Wm    = (const float*)d_in[1];
    const int*   vlen  = (const int*)d_in[2];
    float* out = (float*)d_out;

    cudaFuncSetAttribute(sattn_mma_kernel,
                         cudaFuncAttributeMaxDynamicSharedMemorySize, SMEM_TOTAL);
    sattn_mma_kernel<<<1024, 256, SMEM_TOTAL>>>(words, Wm, vlen, out);
}

// round 9
// speedup vs baseline: 1.2066x; 1.0129x over previous
#include <cuda_runtime.h>
#include <cuda_bf16.h>
#include <cstdint>

// smem: X hi/lo = 256x128 bf16 (row stride 256B, XOR-swizzled). W hi/lo = 128x128 bf16
// ([k][n]); after GEMM1 the W region is reused as XW hi/lo.
#define XH_OFF 0
#define XL_OFF 65536
#define WH_OFF 131072
#define WL_OFF 163840
#define SMEM_TOTAL 196608

__device__ __forceinline__ uint32_t smem_u32(const void* p) {
    uint32_t a;
    asm("{ .reg .u64 t; cvta.to.shared.u64 t, %1; cvt.u32.u64 %0, t; }" : "=r"(a) : "l"(p));
    return a;
}
__device__ __forceinline__ uint32_t soff(uint32_t region, int row, int byte) {
    return region + (uint32_t)(row * 256 + (byte ^ ((row & 7) << 4)));
}
__device__ __forceinline__ void ldsm4(uint32_t addr, uint32_t (&r)[4]) {
    asm volatile("ldmatrix.sync.aligned.m8n8.x4.shared.b16 {%0,%1,%2,%3}, [%4];"
                 : "=r"(r[0]), "=r"(r[1]), "=r"(r[2]), "=r"(r[3]) : "r"(addr));
}
__device__ __forceinline__ void ldsm4t(uint32_t addr, uint32_t (&r)[4]) {
    asm volatile("ldmatrix.sync.aligned.m8n8.x4.trans.shared.b16 {%0,%1,%2,%3}, [%4];"
                 : "=r"(r[0]), "=r"(r[1]), "=r"(r[2]), "=r"(r[3]) : "r"(addr));
}
__device__ __forceinline__ void mma16816(float (&c)[4], const uint32_t (&a)[4],
                                         uint32_t b0, uint32_t b1) {
    asm volatile("mma.sync.aligned.m16n8k16.row.col.f32.bf16.bf16.f32 "
                 "{%0,%1,%2,%3}, {%4,%5,%6,%7}, {%8,%9}, {%0,%1,%2,%3};"
                 : "+f"(c[0]), "+f"(c[1]), "+f"(c[2]), "+f"(c[3])
                 : "r"(a[0]), "r"(a[1]), "r"(a[2]), "r"(a[3]), "r"(b0), "r"(b1));
}
__device__ __forceinline__ uint32_t bpack(float x, float y) {
    __nv_bfloat162 h = __floats2bfloat162_rn(x, y);
    return *reinterpret_cast<uint32_t*>(&h);
}
__device__ __forceinline__ uint32_t bpacklo(float x, float y) {
    float hx = __bfloat162float(__float2bfloat16_rn(x));
    float hy = __bfloat162float(__float2bfloat16_rn(y));
    return bpack(x - hx, y - hy);
}

__global__ void __launch_bounds__(256, 1)
sattn_mma_kernel(const float* __restrict__ words, const float* __restrict__ Wm,
                 const int* __restrict__ vlen, float* __restrict__ out)
{
    extern __shared__ __align__(1024) char smem[];
    const uint32_t sb = smem_u32(smem);
    const int tid = threadIdx.x, lane = tid & 31, warp = tid >> 5;
    const int sent = blockIdx.x >> 1, q0 = (blockIdx.x & 1) * 128;
    const float* xg = words + (size_t)sent * 256 * 128;
    const int len = vlen[sent];
    const int g = lane >> 2, q4 = lane & 3;

    // ---- load X -> XH/XL ----
    for (int i = tid; i < 8192; i += 256) {
        float4 v = ((const float4*)xg)[i];
        int t = i >> 5, b = (i & 31) << 3;
        uint2 hw, lw;
        hw.x = bpack(v.x, v.y); hw.y = bpack(v.z, v.w);
        lw.x = bpacklo(v.x, v.y); lw.y = bpacklo(v.z, v.w);
        *(uint2*)(smem + soff(XH_OFF, t, b)) = hw;
        *(uint2*)(smem + soff(XL_OFF, t, b)) = lw;
    }
    // ---- load W ([k][n]) -> WH/WL ----
    for (int i = tid; i < 4096; i += 256) {
        float4 v = ((const float4*)Wm)[i];
        int k = i >> 5, b = (i & 31) << 3;
        uint2 hw, lw;
        hw.x = bpack(v.x, v.y); hw.y = bpack(v.z, v.w);
        lw.x = bpacklo(v.x, v.y); lw.y = bpacklo(v.z, v.w);
        *(uint2*)(smem + soff(WH_OFF, k, b)) = hw;
        *(uint2*)(smem + soff(WL_OFF, k, b)) = lw;
    }
    __syncthreads();

    const int r0 = q0 + warp * 16;

    // ===== GEMM1: XW[16 x 128] = Xq @ W (3 passes; 16-accumulator rotation) =====
    {
        float xw[16][4];
        #pragma unroll
        for (int j = 0; j < 16; ++j) { xw[j][0] = xw[j][1] = xw[j][2] = xw[j][3] = 0.f; }

        #pragma unroll
        for (int kt = 0; kt < 8; ++kt) {
            uint32_t Ah[4], Al[4];
            {
                int row = r0 + (lane & 15);
                int byt = kt * 32 + ((lane >> 4) << 4);
                ldsm4(sb + soff(XH_OFF, row, byt), Ah);
                ldsm4(sb + soff(XL_OFF, row, byt), Al);
            }
            const int rr = kt * 16 + (lane & 7) + (((lane >> 3) & 1) << 3);
            #pragma unroll
            for (int pass = 0; pass < 3; ++pass) {
                const uint32_t breg = (pass == 1) ? WL_OFF : WH_OFF;
                #pragma unroll
                for (int nn = 0; nn < 8; ++nn) {
                    uint32_t B[4];
                    int bb = (nn * 16 + ((lane >> 4) << 3)) * 2;
                    ldsm4t(sb + soff(breg, rr, bb), B);
                    if (pass == 2) {
                        mma16816(xw[2 * nn],     Al, B[0], B[1]);
                        mma16816(xw[2 * nn + 1], Al, B[2], B[3]);
                    } else {
                        mma16816(xw[2 * nn],     Ah, B[0], B[1]);
                        mma16816(xw[2 * nn + 1], Ah, B[2], B[3]);
                    }
                }
            }
        }
        __syncthreads();   // all warps done reading W

        // store XW hi/lo into the W region (rows are warp-private)
        #pragma unroll
        for (int j = 0; j < 16; ++j) {
            int nbyte = 2 * (8 * j + 2 * q4);
            *(uint32_t*)(smem + soff(WH_OFF, warp * 16 + g,     nbyte)) = bpack(xw[j][0], xw[j][1]);
            *(uint32_t*)(smem + soff(WL_OFF, warp * 16 + g,     nbyte)) = bpacklo(xw[j][0], xw[j][1]);
            *(uint32_t*)(smem + soff(WH_OFF, warp * 16 + g + 8, nbyte)) = bpack(xw[j][2], xw[j][3]);
            *(uint32_t*)(smem + soff(WL_OFF, warp * 16 + g + 8, nbyte)) = bpacklo(xw[j][2], xw[j][3]);
        }
        __syncwarp();
    }

    // ===== fused per 64-key tile: GEMM2 -> exp/mask -> partial GEMM3 =====
    float oa[16][4];
    #pragma unroll
    for (int j = 0; j < 16; ++j) { oa[j][0] = oa[j][1] = oa[j][2] = oa[j][3] = 0.f; }
    float sa0 = 0.f, sm0 = 0.f, sa1 = 0.f, sm1 = 0.f;

    #pragma unroll
    for (int ti = 0; ti < 4; ++ti) {
        const int kb = ti * 64;
        float la[8][4];
        #pragma unroll
        for (int j = 0; j < 8; ++j) { la[j][0] = la[j][1] = la[j][2] = la[j][3] = 0.f; }

        // GEMM2 tile: L[16 x 64] = XW @ X[kb..kb+64]^T (8-accumulator rotation)
        #pragma unroll
        for (int kt = 0; kt < 8; ++kt) {
            uint32_t Ah[4], Al[4];
            {
                int row = warp * 16 + (lane & 15);
                int byt = kt * 32 + ((lane >> 4) << 4);
                ldsm4(sb + soff(WH_OFF, row, byt), Ah);
                ldsm4(sb + soff(WL_OFF, row, byt), Al);
            }
            uint32_t Bh[4][4], Bl[4][4];
            {
                const int rrb = (lane & 7) + ((lane >> 4) << 3);
                const int bb = kt * 32 + (((lane >> 3) & 1) << 4);
                #pragma unroll
                for (int nn = 0; nn < 4; ++nn) {
                    ldsm4(sb + soff(XH_OFF, kb + nn * 16 + rrb, bb), Bh[nn]);
                    ldsm4(sb + soff(XL_OFF, kb + nn * 16 + rrb, bb), Bl[nn]);
                }
            }
            #pragma unroll
            for (int nn = 0; nn < 4; ++nn) {
                mma16816(la[2 * nn],     Ah, Bh[nn][0], Bh[nn][1]);
                mma16816(la[2 * nn + 1], Ah, Bh[nn][2], Bh[nn][3]);
            }
            #pragma unroll
            for (int nn = 0; nn < 4; ++nn) {
                mma16816(la[2 * nn],     Ah, Bl[nn][0], Bl[nn][1]);
                mma16816(la[2 * nn + 1], Ah, Bl[nn][2], Bl[nn][3]);
            }
            #pragma unroll
            for (int nn = 0; nn < 4; ++nn) {
                mma16816(la[2 * nn],     Al, Bh[nn][0], Bh[nn][1]);
                mma16816(la[2 * nn + 1], Al, Bh[nn][2], Bh[nn][3]);
            }
        }

        // tanh -> exp -> mask (unnormalized; row sums accumulated)
        #pragma unroll
        for (int j = 0; j < 8; ++j) {
            int tb = kb + 8 * j + 2 * q4;
            #pragma unroll
            for (int c = 0; c < 2; ++c) {
                const bool m = (tb + c) < len;
                {
                    float l = la[j][c];
                    float u = __expf(2.f * l);
                    float t2 = 1.f - __fdividef(2.f, u + 1.f);
                    float w = __expf(t2);
                    float wm = m ? w : 0.f;
                    sa0 += w; sm0 += wm; la[j][c] = wm;
                }
                {
                    float l = la[j][2 + c];
                    float u = __expf(2.f * l);
                    float t2 = 1.f - __fdividef(2.f, u + 1.f);
                    float w = __expf(t2);
                    float wm = m ? w : 0.f;
                    sa1 += w; sm1 += wm; la[j][2 + c] = wm;
                }
            }
        }

        // pack P fragments for the 4 16-key chunks of this tile
        uint32_t ph[4][4], pl[4][4];
        #pragma unroll
        for (int kt = 0; kt < 4; ++kt) {
            ph[kt][0] = bpack(la[2 * kt][0], la[2 * kt][1]);
            ph[kt][1] = bpack(la[2 * kt][2], la[2 * kt][3]);
            ph[kt][2] = bpack(la[2 * kt + 1][0], la[2 * kt + 1][1]);
            ph[kt][3] = bpack(la[2 * kt + 1][2], la[2 * kt + 1][3]);
            pl[kt][0] = bpacklo(la[2 * kt][0], la[2 * kt][1]);
            pl[kt][1] = bpacklo(la[2 * kt][2], la[2 * kt][3]);
            pl[kt][2] = bpacklo(la[2 * kt + 1][0], la[2 * kt + 1][1]);
            pl[kt][3] = bpacklo(la[2 * kt + 1][2], la[2 * kt + 1][3]);
        }

        // GEMM3 partial: oa += w_tile @ X[kb..kb+64] (3 passes; 16-acc rotation)
        #pragma unroll
        for (int kt = 0; kt < 4; ++kt) {
            const int rr = kb + kt * 16 + (lane & 7) + (((lane >> 3) & 1) << 3);
            #pragma unroll
            for (int pass = 0; pass < 3; ++pass) {
                const uint32_t breg = (pass == 1) ? XL_OFF : XH_OFF;
                #pragma unroll
                for (int nn = 0; nn < 8; ++nn) {
                    uint32_t B[4];
                    int bb = (nn * 16 + ((lane >> 4) << 3)) * 2;
                    ldsm4t(sb + soff(breg, rr, bb), B);
                    if (pass == 2) {
                        mma16816(oa[2 * nn],     pl[kt], B[0], B[1]);
                        mma16816(oa[2 * nn + 1], pl[kt], B[2], B[3]);
                    } else {
                        mma16816(oa[2 * nn],     ph[kt], B[0], B[1]);
                        mma16816(oa[2 * nn + 1], ph[kt], B[2], B[3]);
                    }
                }
            }
        }
    }

    // ===== row sums -> inverse -> scale -> store =====
    #pragma unroll
    for (int off = 1; off <= 2; off <<= 1) {
        sa0 += __shfl_xor_sync(0xffffffffu, sa0, off);
        sm0 += __shfl_xor_sync(0xffffffffu, sm0, off);
        sa1 += __shfl_xor_sync(0xffffffffu, sa1, off);
        sm1 += __shfl_xor_sync(0xffffffffu, sm1, off);
    }
    const float inv0 = 1.f / (sm0 + 1e-8f * sa0);
    const float inv1 = 1.f / (sm1 + 1e-8f * sa1);

    {
        const size_t rbase = (size_t)sent * 256 + r0;
        #pragma unroll
        for (int j = 0; j < 16; ++j) {
            int col = 8 * j + 2 * q4;
            float2 v0; v0.x = oa[j][0] * inv0; v0.y = oa[j][1] * inv0;
            float2 v1; v1.x = oa[j][2] * inv1; v1.y = oa[j][3] * inv1;
            *(float2*)(out + (rbase + g) * 128 + col) = v0;
            *(float2*)(out + (rbase + g + 8) * 128 + col) = v1;
        }
    }
}

extern "C" void kernel_launch(void* const* d_in, const int* in_sizes, int n_in,
                              void* d_out, int out_size)
{
    const float* words = (const float*)d_in[0];
    const float* Wm    = (const float*)d_in[1];
    const int*   vlen  = (const int*)d_in[2];
    float* out = (float*)d_out;

    cudaFuncSetAttribute(sattn_mma_kernel,
                         cudaFuncAttributeMaxDynamicSharedMemorySize, SMEM_TOTAL);
    sattn_mma_kernel<<<1024, 256, SMEM_TOTAL>>>(words, Wm, vlen, out);
}